// round 1
// baseline (speedup 1.0000x reference)
#include <cuda_runtime.h>

#define TT 4
#define BB 16
#define NTOK 1024
#define CC 512
#define BNC (BB*NTOK*CC)        /* 8388608  */
#define TBNC (TT*BNC)           /* 33554432 */
#define MROWS (TT*BB*NTOK)      /* 65536    */

// ---------------- scratch (static device globals; no allocation) ----------------
__device__ unsigned char g_xs[TBNC];
__device__ unsigned char g_qs[TBNC];
__device__ unsigned char g_ks[TBNC];
__device__ unsigned char g_vs[TBNC];
__device__ unsigned char g_att[TBNC];
__device__ float         g_Y[TBNC];
__device__ int           g_kvcnt[TT*BB*8*64];
__device__ unsigned char g_kvspk[TT*BB*8*64];

// ---------------- LIF over input x -> xs spikes ----------------
__global__ void lif_x_kernel(const float* __restrict__ x)
{
    int i = blockIdx.x * blockDim.x + threadIdx.x;   // over BNC/4
    if (i >= BNC/4) return;
    const float4* x4 = (const float4*)x;
    uchar4* xs4 = (uchar4*)g_xs;
    float4 v = make_float4(0.f,0.f,0.f,0.f);
    #pragma unroll
    for (int t = 0; t < TT; t++) {
        float4 xv = x4[t*(BNC/4) + i];
        v.x += (xv.x - v.x) * 0.5f;
        v.y += (xv.y - v.y) * 0.5f;
        v.z += (xv.z - v.z) * 0.5f;
        v.w += (xv.w - v.w) * 0.5f;
        uchar4 s;
        s.x = (v.x - 1.0f >= 0.f); if (s.x) v.x = 0.f;
        s.y = (v.y - 1.0f >= 0.f); if (s.y) v.y = 0.f;
        s.z = (v.z - 1.0f >= 0.f); if (s.z) v.z = 0.f;
        s.w = (v.w - 1.0f >= 0.f); if (s.w) v.w = 0.f;
        xs4[t*(BNC/4) + i] = s;
    }
}

// ---------------- fp32 SIMT GEMM: Y[M,512] = A(u8,{0,1})[M,512] @ W[512,512] ----------------
#define LOAD_TILE(k0) do { \
    if (tid < 128) areg = *(const uint4*)(Ag + tid*512 + (k0)); \
    wreg0 = *(const float4*)(Wg + ((k0)+wk)*512 + wc); \
    wreg1 = *(const float4*)(Wg + ((k0)+wk+8)*512 + wc); \
} while(0)

#define STORE_TILE(buf) do { \
    if (tid < 128) { unsigned w; \
        w=areg.x; As[buf][ 0][tid]=(float)(w&255u); As[buf][ 1][tid]=(float)((w>>8)&255u); As[buf][ 2][tid]=(float)((w>>16)&255u); As[buf][ 3][tid]=(float)(w>>24); \
        w=areg.y; As[buf][ 4][tid]=(float)(w&255u); As[buf][ 5][tid]=(float)((w>>8)&255u); As[buf][ 6][tid]=(float)((w>>16)&255u); As[buf][ 7][tid]=(float)(w>>24); \
        w=areg.z; As[buf][ 8][tid]=(float)(w&255u); As[buf][ 9][tid]=(float)((w>>8)&255u); As[buf][10][tid]=(float)((w>>16)&255u); As[buf][11][tid]=(float)(w>>24); \
        w=areg.w; As[buf][12][tid]=(float)(w&255u); As[buf][13][tid]=(float)((w>>8)&255u); As[buf][14][tid]=(float)((w>>16)&255u); As[buf][15][tid]=(float)(w>>24); \
    } \
    *(float4*)&Ws[buf][wk  ][wc] = wreg0; \
    *(float4*)&Ws[buf][wk+8][wc] = wreg1; \
} while(0)

__global__ __launch_bounds__(256, 2) void gemm_kernel(const float* __restrict__ W, int use_att)
{
    const unsigned char* Abase = use_att ? g_att : g_xs;
    __shared__ float As[2][16][128];
    __shared__ float Ws[2][16][128];
    const int tid = threadIdx.x;
    const int bx = blockIdx.x;          // n tile: 0..3
    const int by = blockIdx.y;          // m tile: 0..511
    const int tx = tid & 15, ty = tid >> 4;
    const unsigned char* Ag = Abase + by * 128 * 512;
    const float* Wg = W + bx * 128;
    const int wk = tid >> 5;            // 0..7
    const int wc = (tid & 31) * 4;      // 0..124

    uint4 areg;
    float4 wreg0, wreg1;

    float acc[8][8];
    #pragma unroll
    for (int i = 0; i < 8; i++)
        #pragma unroll
        for (int j = 0; j < 8; j++) acc[i][j] = 0.f;

    LOAD_TILE(0);
    STORE_TILE(0);
    __syncthreads();

    for (int kt = 0; kt < 32; kt++) {
        const int buf = kt & 1;
        if (kt < 31) LOAD_TILE((kt+1)*16);
        #pragma unroll
        for (int k = 0; k < 16; k++) {
            float4 a0 = *(const float4*)&As[buf][k][ty*8];
            float4 a1 = *(const float4*)&As[buf][k][ty*8+4];
            float4 b0 = *(const float4*)&Ws[buf][k][tx*8];
            float4 b1 = *(const float4*)&Ws[buf][k][tx*8+4];
            float av[8] = {a0.x,a0.y,a0.z,a0.w,a1.x,a1.y,a1.z,a1.w};
            float bv[8] = {b0.x,b0.y,b0.z,b0.w,b1.x,b1.y,b1.z,b1.w};
            #pragma unroll
            for (int i = 0; i < 8; i++)
                #pragma unroll
                for (int j = 0; j < 8; j++)
                    acc[i][j] += av[i] * bv[j];
        }
        if (kt < 31) { STORE_TILE(buf ^ 1); __syncthreads(); }
    }

    float* Yg = g_Y + (by*128 + ty*8)*512 + bx*128 + tx*8;
    #pragma unroll
    for (int i = 0; i < 8; i++) {
        *(float4*)(Yg + i*512)     = make_float4(acc[i][0],acc[i][1],acc[i][2],acc[i][3]);
        *(float4*)(Yg + i*512 + 4) = make_float4(acc[i][4],acc[i][5],acc[i][6],acc[i][7]);
    }
}

// ---------------- bn + LIF over Y -> spikes (q/k/v); optionally emit fp32 v output ----------------
__global__ void lif_bn_kernel(const float* __restrict__ bias,
                              const float* __restrict__ bnp,
                              int sel, float* __restrict__ vout)
{
    int i = blockIdx.x * blockDim.x + threadIdx.x;   // over BNC/4
    if (i >= BNC/4) return;
    const int c = (i & 127) * 4;
    float4 ga = *(const float4*)(bnp + c);
    float4 be = *(const float4*)(bnp + 512 + c);
    float4 mu = *(const float4*)(bnp + 1024 + c);
    float4 va = *(const float4*)(bnp + 1536 + c);
    float4 rs;
    rs.x = 1.f/sqrtf(va.x + 1e-5f); rs.y = 1.f/sqrtf(va.y + 1e-5f);
    rs.z = 1.f/sqrtf(va.z + 1e-5f); rs.w = 1.f/sqrtf(va.w + 1e-5f);
    float4 bb = make_float4(0.f,0.f,0.f,0.f);
    if (bias) bb = *(const float4*)(bias + c);

    unsigned char* dst = (sel == 0) ? g_qs : (sel == 1) ? g_ks : g_vs;
    uchar4* dst4 = (uchar4*)dst;
    const float4* Y4 = (const float4*)g_Y;

    // decode for v output layout (T,B,H,N,D)
    const int b = i >> 17;               // 131072 float4 per batch
    const int r = i & 131071;
    const int n = r >> 7;
    const int h = c >> 6;
    const int d = c & 63;

    float4 v = make_float4(0.f,0.f,0.f,0.f);
    #pragma unroll
    for (int t = 0; t < TT; t++) {
        float4 y = Y4[t*(BNC/4) + i];
        float ux = ga.x * ((y.x + bb.x) - mu.x) * rs.x + be.x;
        float uy = ga.y * ((y.y + bb.y) - mu.y) * rs.y + be.y;
        float uz = ga.z * ((y.z + bb.z) - mu.z) * rs.z + be.z;
        float uw = ga.w * ((y.w + bb.w) - mu.w) * rs.w + be.w;
        v.x += (ux - v.x) * 0.5f;
        v.y += (uy - v.y) * 0.5f;
        v.z += (uz - v.z) * 0.5f;
        v.w += (uw - v.w) * 0.5f;
        uchar4 s;
        s.x = (v.x - 1.0f >= 0.f); if (s.x) v.x = 0.f;
        s.y = (v.y - 1.0f >= 0.f); if (s.y) v.y = 0.f;
        s.z = (v.z - 1.0f >= 0.f); if (s.z) v.z = 0.f;
        s.w = (v.w - 1.0f >= 0.f); if (s.w) v.w = 0.f;
        dst4[t*(BNC/4) + i] = s;
        if (sel == 2 && vout) {
            float4 fs = make_float4((float)s.x,(float)s.y,(float)s.z,(float)s.w);
            *(float4*)(vout + ((((size_t)(t*BB + b)*8 + h)*1024 + n)*64 + d)) = fs;
        }
    }
}

// ---------------- kv = sum_n k*v (integer-exact) ----------------
__global__ void kv_count_kernel()
{
    const int bid = blockIdx.x;          // (t*16+b)*8+h, 512 blocks
    const int tid = threadIdx.x;         // 256
    const int d4 = tid & 15, g = tid >> 4;
    const int h = bid & 7;
    const int tb = bid >> 3;
    const int base = tb * 1024 * 512 + h * 64 + d4 * 4;
    int a0=0,a1=0,a2=0,a3=0;
    for (int nn = 0; nn < 64; nn++) {
        int off = base + (g*64 + nn) * 512;
        uchar4 kk = *(const uchar4*)(g_ks + off);
        uchar4 vv = *(const uchar4*)(g_vs + off);
        a0 += kk.x & vv.x; a1 += kk.y & vv.y; a2 += kk.z & vv.z; a3 += kk.w & vv.w;
    }
    __shared__ int4 s[16][16];
    s[g][d4] = make_int4(a0,a1,a2,a3);
    __syncthreads();
    if (tid < 16) {
        int4 tot = make_int4(0,0,0,0);
        #pragma unroll
        for (int gg = 0; gg < 16; gg++) {
            tot.x += s[gg][tid].x; tot.y += s[gg][tid].y;
            tot.z += s[gg][tid].z; tot.w += s[gg][tid].w;
        }
        ((int4*)g_kvcnt)[bid*16 + tid] = tot;
    }
}

__global__ void lif_kv_kernel()
{
    int i = blockIdx.x * blockDim.x + threadIdx.x;   // BB*8*64 = 8192
    if (i >= BB*8*64) return;
    float m = 0.f;
    #pragma unroll
    for (int t = 0; t < TT; t++) {
        float cnt = (float)g_kvcnt[t*8192 + i];
        m += (cnt - m) * 0.5f;
        unsigned char s = (m - 0.5f >= 0.f);
        g_kvspk[t*8192 + i] = s;
        if (s) m = 0.f;
    }
}

// ---------------- att = q * kv_spk (broadcast over n) ----------------
__global__ void att_kernel()
{
    int i = blockIdx.x * blockDim.x + threadIdx.x;   // TBNC/4
    if (i >= TBNC/4) return;
    const int c4  = i & 127;
    const int tbn = i >> 7;
    const int tb  = tbn >> 10;
    const int h   = c4 >> 4;
    const int d4  = c4 & 15;
    uchar4 q = ((const uchar4*)g_qs)[i];
    uchar4 kv = *(const uchar4*)(g_kvspk + (tb*8 + h)*64 + d4*4);
    uchar4 a;
    a.x = q.x & kv.x; a.y = q.y & kv.y; a.z = q.z & kv.z; a.w = q.w & kv.w;
    ((uchar4*)g_att)[i] = a;
}

// ---------------- final bn + identity ----------------
__global__ void out_kernel(const float* __restrict__ x,
                           const float* __restrict__ bp,
                           const float* __restrict__ bnp,
                           float* __restrict__ out)
{
    int i = blockIdx.x * blockDim.x + threadIdx.x;   // TBNC/4
    if (i >= TBNC/4) return;
    const int c = (i & 127) * 4;
    float4 ga = *(const float4*)(bnp + c);
    float4 be = *(const float4*)(bnp + 512 + c);
    float4 mu = *(const float4*)(bnp + 1024 + c);
    float4 va = *(const float4*)(bnp + 1536 + c);
    float4 b  = *(const float4*)(bp + c);
    float4 y  = ((const float4*)g_Y)[i];
    float4 xv = ((const float4*)x)[i];
    float4 o;
    o.x = ga.x * ((y.x + b.x) - mu.x) * (1.f/sqrtf(va.x + 1e-5f)) + be.x + xv.x;
    o.y = ga.y * ((y.y + b.y) - mu.y) * (1.f/sqrtf(va.y + 1e-5f)) + be.y + xv.y;
    o.z = ga.z * ((y.z + b.z) - mu.z) * (1.f/sqrtf(va.z + 1e-5f)) + be.z + xv.z;
    o.w = ga.w * ((y.w + b.w) - mu.w) * (1.f/sqrtf(va.w + 1e-5f)) + be.w + xv.w;
    ((float4*)out)[i] = o;
}

// ---------------- launch ----------------
extern "C" void kernel_launch(void* const* d_in, const int* in_sizes, int n_in,
                              void* d_out, int out_size)
{
    const float* x    = (const float*)d_in[0];
    const float* Wq   = (const float*)d_in[1];
    const float* bq   = (const float*)d_in[2];
    const float* Wk   = (const float*)d_in[3];
    const float* bk   = (const float*)d_in[4];
    const float* Wv   = (const float*)d_in[5];
    const float* Wp   = (const float*)d_in[6];
    const float* bp   = (const float*)d_in[7];
    const float* bn_q = (const float*)d_in[8];
    const float* bn_k = (const float*)d_in[9];
    const float* bn_v = (const float*)d_in[10];
    const float* bn_p = (const float*)d_in[11];
    float* out  = (float*)d_out;
    float* vout = (out_size >= 2*TBNC) ? (out + TBNC) : nullptr;

    const dim3 gemm_grid(4, 512);

    lif_x_kernel<<<(BNC/4 + 255)/256, 256>>>(x);

    gemm_kernel<<<gemm_grid, 256>>>(Wq, 0);
    lif_bn_kernel<<<(BNC/4 + 255)/256, 256>>>(bq, bn_q, 0, nullptr);

    gemm_kernel<<<gemm_grid, 256>>>(Wk, 0);
    lif_bn_kernel<<<(BNC/4 + 255)/256, 256>>>(bk, bn_k, 1, nullptr);

    gemm_kernel<<<gemm_grid, 256>>>(Wv, 0);
    lif_bn_kernel<<<(BNC/4 + 255)/256, 256>>>(nullptr, bn_v, 2, vout);

    kv_count_kernel<<<TT*BB*8, 256>>>();
    lif_kv_kernel<<<(BB*8*64 + 255)/256, 256>>>();

    att_kernel<<<(TBNC/4 + 255)/256, 256>>>();

    gemm_kernel<<<gemm_grid, 256>>>(Wp, 1);
    out_kernel<<<(TBNC/4 + 255)/256, 256>>>(x, bp, bn_p, out);
}

// round 10
// speedup vs baseline: 2.6236x; 2.6236x over previous
#include <cuda_runtime.h>
#include <cuda_bf16.h>
#include <cstdint>

#define TT 4
#define BB 16
#define NTOK 1024
#define CC 512
#define BNC (BB*NTOK*CC)        /* 8388608  */
#define TBNC (TT*BNC)           /* 33554432 */

// ---------------- scratch ----------------
__device__ __nv_bfloat16 g_xs_bf[TBNC];
__device__ __nv_bfloat16 g_k_bf[TBNC];
__device__ __nv_bfloat16 g_v_bf[TBNC];
__device__ __nv_bfloat16 g_att_bf[TBNC];
__device__ float         g_Y[TBNC];
__device__ __nv_bfloat16 g_wt[4][3][CC*CC];
__device__ int           g_kvcnt[TT*BB*8*64];
__device__ unsigned short g_kvspk[TT*BB*8*64];

// ---------------- PTX helpers (sm_80-compatible only; NO tcgen05) ----------------
__device__ __forceinline__ uint32_t smem_u32(const void* p) {
    uint32_t a;
    asm("{ .reg .u64 t; cvta.to.shared.u64 t, %1; cvt.u32.u64 %0, t; }" : "=r"(a) : "l"(p));
    return a;
}
__device__ __forceinline__ void cp_async16(uint32_t dst, const void* src) {
    asm volatile("cp.async.cg.shared.global [%0], [%1], 16;" :: "r"(dst), "l"(src));
}
#define CP_COMMIT() asm volatile("cp.async.commit_group;" ::: "memory")
#define CP_WAIT(n)  asm volatile("cp.async.wait_group %0;" ::"n"(n) : "memory")

__device__ __forceinline__ void ldsm4(uint32_t& r0, uint32_t& r1, uint32_t& r2, uint32_t& r3, uint32_t addr) {
    asm volatile("ldmatrix.sync.aligned.m8n8.x4.shared.b16 {%0,%1,%2,%3}, [%4];"
                 : "=r"(r0), "=r"(r1), "=r"(r2), "=r"(r3) : "r"(addr));
}
__device__ __forceinline__ void mma_bf16(float* c, const uint32_t* a, const uint32_t* b) {
    asm volatile("mma.sync.aligned.m16n8k16.row.col.f32.bf16.bf16.f32 "
                 "{%0,%1,%2,%3}, {%4,%5,%6,%7}, {%8,%9}, {%0,%1,%2,%3};"
                 : "+f"(c[0]), "+f"(c[1]), "+f"(c[2]), "+f"(c[3])
                 : "r"(a[0]), "r"(a[1]), "r"(a[2]), "r"(a[3]), "r"(b[0]), "r"(b[1]));
}

// ---------------- weight split + transpose: g_wt[w][s][n*512+k] ----------------
__global__ void wsplit_kernel(const float* __restrict__ W, int widx)
{
    __shared__ float t[32][33];
    int bx = blockIdx.x & 15, by = blockIdx.x >> 4;
    int x = threadIdx.x & 31, y = threadIdx.x >> 5;   // y: 0..7
    #pragma unroll
    for (int i = 0; i < 4; i++)
        t[y + 8*i][x] = W[(by*32 + y + 8*i)*512 + bx*32 + x];
    __syncthreads();
    #pragma unroll
    for (int i = 0; i < 4; i++) {
        float w = t[x][y + 8*i];
        int n = bx*32 + y + 8*i, k = by*32 + x;
        __nv_bfloat16 h0 = __float2bfloat16(w);
        float r1 = w - __bfloat162float(h0);
        __nv_bfloat16 h1 = __float2bfloat16(r1);
        float r2 = r1 - __bfloat162float(h1);
        __nv_bfloat16 h2 = __float2bfloat16(r2);
        size_t o = (size_t)n*512 + k;
        g_wt[widx][0][o] = h0; g_wt[widx][1][o] = h1; g_wt[widx][2][o] = h2;
    }
}

// ---------------- HMMA GEMM: Y[M,512] = A(bf16 {0,1})[M,512] @ (w0+w1+w2)^ (BT [n][k]) ----------------
// CTA 128x128, 8 warps (2x4), warp tile 64x32. K: 8 chunks of 64, x3 splits = 24 stages.
#define GSMEM_BYTES (65536 + 1024)

__device__ __forceinline__ void load_tile_128(uint32_t buf, const __nv_bfloat16* src, int kc, int tid)
{
    // 128 rows x 64 bf16 (128B/row), SW128-xor swizzled; src row stride 512 bf16 (1024B)
    const char* s0 = (const char*)src + kc*128;
    #pragma unroll
    for (int it = 0; it < 4; it++) {
        int idx = it*256 + tid;              // 0..1023
        int r = idx >> 3, c16 = idx & 7;
        uint32_t off = (uint32_t)r*128 + c16*16;
        cp_async16(buf + (off ^ ((off >> 3) & 0x70)), s0 + (size_t)r*1024 + c16*16);
    }
}

__global__ __launch_bounds__(256, 2) void gemm_mma_kernel(int widx, int use_att)
{
    extern __shared__ char dsm[];
    uint32_t sb = (smem_u32(dsm) + 1023) & ~1023u;
    const uint32_t A_OFF = sb;               // 2 x 16KB
    const uint32_t B_OFF = sb + 32768;       // 2 x 16KB
    const int tid = threadIdx.x, lane = tid & 31, wid = tid >> 5;
    const int wm = wid >> 2, wn = wid & 3;   // warp grid 2(M) x 4(N)

    const int by = blockIdx.x >> 2, bx = blockIdx.x & 3;
    const __nv_bfloat16* Asrc = (use_att ? g_att_bf : g_xs_bf) + (size_t)by*128*512;
    const __nv_bfloat16* Wsrc0 = g_wt[widx][0] + (size_t)bx*128*512;
    const __nv_bfloat16* Wsrc1 = g_wt[widx][1] + (size_t)bx*128*512;
    const __nv_bfloat16* Wsrc2 = g_wt[widx][2] + (size_t)bx*128*512;

    float acc[4][4][4];
    #pragma unroll
    for (int i = 0; i < 4; i++)
        #pragma unroll
        for (int j = 0; j < 4; j++)
            #pragma unroll
            for (int q = 0; q < 4; q++) acc[i][j][q] = 0.f;

    // stage s: kc = s/3, split = s%3. A loaded when split==0 into A[kc&1]; B into B[s&1].
    // prologue: stages 0,1
    load_tile_128(A_OFF, Asrc, 0, tid);
    load_tile_128(B_OFF, Wsrc0, 0, tid);
    CP_COMMIT();
    load_tile_128(B_OFF + 16384, Wsrc1, 0, tid);
    CP_COMMIT();

    int kc = 0, split = 0;
    for (int s = 0; s < 24; s++) {
        if (s < 23) CP_WAIT(1); else CP_WAIT(0);
        __syncthreads();

        // compute stage s
        {
            uint32_t abase = A_OFF + (kc & 1)*16384;
            uint32_t bbase = B_OFF + (s & 1)*16384;
            #pragma unroll
            for (int k16 = 0; k16 < 4; k16++) {
                uint32_t a[4][4];
                #pragma unroll
                for (int mb = 0; mb < 4; mb++) {
                    uint32_t row = wm*64 + mb*16 + (lane & 15);
                    uint32_t kb  = k16*32 + ((lane >> 4) << 4);
                    uint32_t off = row*128 + kb;
                    ldsm4(a[mb][0], a[mb][1], a[mb][2], a[mb][3],
                          abase + (off ^ ((off >> 3) & 0x70)));
                }
                uint32_t b[4][2];
                #pragma unroll
                for (int nb2 = 0; nb2 < 2; nb2++) {
                    uint32_t row = wn*32 + nb2*16 + (lane & 7) + ((lane >> 4) << 3);
                    uint32_t kb  = k16*32 + (((lane >> 3) & 1) << 4);
                    uint32_t off = row*128 + kb;
                    ldsm4(b[nb2*2][0], b[nb2*2][1], b[nb2*2+1][0], b[nb2*2+1][1],
                          bbase + (off ^ ((off >> 3) & 0x70)));
                }
                #pragma unroll
                for (int mb = 0; mb < 4; mb++)
                    #pragma unroll
                    for (int nb = 0; nb < 4; nb++)
                        mma_bf16(acc[mb][nb], a[mb], b[nb]);
            }
        }
        __syncthreads();

        // advance + issue stage s+2 loads
        split++; if (split == 3) { split = 0; kc++; }
        if (s + 2 < 24) {
            int s2 = s + 2;
            int kc2 = s2 / 3, sp2 = s2 - kc2*3;
            if (sp2 == 0) load_tile_128(A_OFF + (kc2 & 1)*16384, Asrc, kc2, tid);
            const __nv_bfloat16* ws = (sp2 == 0) ? Wsrc0 : (sp2 == 1) ? Wsrc1 : Wsrc2;
            load_tile_128(B_OFF + (s2 & 1)*16384, ws, kc2, tid);
            CP_COMMIT();
        }
    }

    // epilogue: write f32 accumulators to g_Y
    const int gq = lane >> 2, qt = lane & 3;
    #pragma unroll
    for (int mb = 0; mb < 4; mb++) {
        #pragma unroll
        for (int nb = 0; nb < 4; nb++) {
            size_t row0 = (size_t)by*128 + wm*64 + mb*16 + gq;
            size_t col  = (size_t)bx*128 + wn*32 + nb*8 + qt*2;
            *(float2*)(g_Y + row0*512 + col)     = make_float2(acc[mb][nb][0], acc[mb][nb][1]);
            *(float2*)(g_Y + (row0+8)*512 + col) = make_float2(acc[mb][nb][2], acc[mb][nb][3]);
        }
    }
}

// ---------------- LIF over input x -> xs spikes (bf16) ----------------
__global__ void lif_x_kernel(const float* __restrict__ x)
{
    int i = blockIdx.x * blockDim.x + threadIdx.x;
    if (i >= BNC/4) return;
    const float4* x4 = (const float4*)x;
    uint2* xs2 = (uint2*)g_xs_bf;
    float4 v = make_float4(0.f, 0.f, 0.f, 0.f);
    #pragma unroll
    for (int t = 0; t < TT; t++) {
        float4 xv = x4[t*(BNC/4) + i];
        v.x += (xv.x - v.x)*0.5f; v.y += (xv.y - v.y)*0.5f;
        v.z += (xv.z - v.z)*0.5f; v.w += (xv.w - v.w)*0.5f;
        unsigned s0 = (v.x >= 1.0f), s1 = (v.y >= 1.0f), s2 = (v.z >= 1.0f), s3 = (v.w >= 1.0f);
        if (s0) v.x = 0.f; if (s1) v.y = 0.f; if (s2) v.z = 0.f; if (s3) v.w = 0.f;
        uint2 o;
        o.x = (s0 ? 0x3F80u : 0u) | ((s1 ? 0x3F80u : 0u) << 16);
        o.y = (s2 ? 0x3F80u : 0u) | ((s3 ? 0x3F80u : 0u) << 16);
        xs2[t*(BNC/4) + i] = o;
    }
}

// ---------------- bn + LIF over Y -> bf16 spikes; sel: 0=q(+att mask), 1=k, 2=v(+vout) ----------------
__global__ void lif_bn_kernel(const float* __restrict__ bias,
                              const float* __restrict__ bnp,
                              int sel, float* __restrict__ vout)
{
    int i = blockIdx.x * blockDim.x + threadIdx.x;
    if (i >= BNC/4) return;
    const int c = (i & 127)*4;
    float4 ga = *(const float4*)(bnp + c);
    float4 be = *(const float4*)(bnp + 512 + c);
    float4 mu = *(const float4*)(bnp + 1024 + c);
    float4 va = *(const float4*)(bnp + 1536 + c);
    float4 rs;
    rs.x = rsqrtf(va.x + 1e-5f); rs.y = rsqrtf(va.y + 1e-5f);
    rs.z = rsqrtf(va.z + 1e-5f); rs.w = rsqrtf(va.w + 1e-5f);
    float4 bb = make_float4(0.f, 0.f, 0.f, 0.f);
    if (bias) bb = *(const float4*)(bias + c);

    uint2* dst = (sel == 0) ? (uint2*)g_att_bf : (sel == 1) ? (uint2*)g_k_bf : (uint2*)g_v_bf;
    const float4* Y4 = (const float4*)g_Y;

    const int b = i >> 17;
    const int r = i & 131071;
    const int n = r >> 7;
    const int h = c >> 6;
    const int d = c & 63;

    float4 v = make_float4(0.f, 0.f, 0.f, 0.f);
    #pragma unroll
    for (int t = 0; t < TT; t++) {
        float4 y = Y4[t*(BNC/4) + i];
        float ux = ga.x*((y.x + bb.x) - mu.x)*rs.x + be.x;
        float uy = ga.y*((y.y + bb.y) - mu.y)*rs.y + be.y;
        float uz = ga.z*((y.z + bb.z) - mu.z)*rs.z + be.z;
        float uw = ga.w*((y.w + bb.w) - mu.w)*rs.w + be.w;
        v.x += (ux - v.x)*0.5f; v.y += (uy - v.y)*0.5f;
        v.z += (uz - v.z)*0.5f; v.w += (uw - v.w)*0.5f;
        unsigned s0 = (v.x >= 1.0f), s1 = (v.y >= 1.0f), s2 = (v.z >= 1.0f), s3 = (v.w >= 1.0f);
        if (s0) v.x = 0.f; if (s1) v.y = 0.f; if (s2) v.z = 0.f; if (s3) v.w = 0.f;
        uint2 o;
        o.x = (s0 ? 0x3F80u : 0u) | ((s1 ? 0x3F80u : 0u) << 16);
        o.y = (s2 ? 0x3F80u : 0u) | ((s3 ? 0x3F80u : 0u) << 16);
        if (sel == 0) {   // q: apply talking-heads kv mask -> att directly
            uint2 mm = *(const uint2*)(g_kvspk + ((t*BB + b)*8 + h)*64 + d);
            o.x &= mm.x; o.y &= mm.y;
        }
        dst[t*(BNC/4) + i] = o;
        if (sel == 2 && vout) {
            float4 fs = make_float4((float)s0, (float)s1, (float)s2, (float)s3);
            *(float4*)(vout + ((((size_t)(t*BB + b)*8 + h)*1024 + n)*64 + d)) = fs;
        }
    }
}

// ---------------- kv = sum_n k*v (integer-exact, bf16 inputs) ----------------
__global__ void kv_count_kernel()
{
    const int bid = blockIdx.x;          // (t*16+b)*8+h
    const int tid = threadIdx.x;         // 256
    const int d4 = tid & 15, g = tid >> 4;
    const int h = bid & 7;
    const int tb = bid >> 3;
    const size_t base = (size_t)tb*1024*512 + h*64 + d4*4;
    int a0=0, a1=0, a2=0, a3=0;
    for (int nn = 0; nn < 64; nn++) {
        size_t off = base + (size_t)(g*64 + nn)*512;
        uint2 kk = *(const uint2*)(g_k_bf + off);
        uint2 vv = *(const uint2*)(g_v_bf + off);
        unsigned m0 = kk.x & vv.x, m1 = kk.y & vv.y;
        a0 += (m0 & 0xFFFFu) ? 1 : 0; a1 += (m0 >> 16) ? 1 : 0;
        a2 += (m1 & 0xFFFFu) ? 1 : 0; a3 += (m1 >> 16) ? 1 : 0;
    }
    __shared__ int4 s[16][16];
    s[g][d4] = make_int4(a0, a1, a2, a3);
    __syncthreads();
    if (tid < 16) {
        int4 tot = make_int4(0, 0, 0, 0);
        #pragma unroll
        for (int gg = 0; gg < 16; gg++) {
            tot.x += s[gg][tid].x; tot.y += s[gg][tid].y;
            tot.z += s[gg][tid].z; tot.w += s[gg][tid].w;
        }
        ((int4*)g_kvcnt)[bid*16 + tid] = tot;
    }
}

__global__ void lif_kv_kernel()
{
    int i = blockIdx.x * blockDim.x + threadIdx.x;   // BB*8*64 = 8192
    if (i >= BB*8*64) return;
    float m = 0.f;
    #pragma unroll
    for (int t = 0; t < TT; t++) {
        float cnt = (float)g_kvcnt[t*8192 + i];
        m += (cnt - m)*0.5f;
        unsigned short sm = (m >= 0.5f) ? 0xFFFFu : 0u;
        g_kvspk[t*8192 + i] = sm;
        if (sm) m = 0.f;
    }
}

// ---------------- final bn + identity ----------------
__global__ void out_kernel(const float* __restrict__ x,
                           const float* __restrict__ bp,
                           const float* __restrict__ bnp,
                           float* __restrict__ out)
{
    int i = blockIdx.x * blockDim.x + threadIdx.x;   // TBNC/4
    if (i >= TBNC/4) return;
    const int c = (i & 127)*4;
    float4 ga = *(const float4*)(bnp + c);
    float4 be = *(const float4*)(bnp + 512 + c);
    float4 mu = *(const float4*)(bnp + 1024 + c);
    float4 va = *(const float4*)(bnp + 1536 + c);
    float4 b  = *(const float4*)(bp + c);
    float4 y  = ((const float4*)g_Y)[i];
    float4 xv = ((const float4*)x)[i];
    float4 o;
    o.x = ga.x*((y.x + b.x) - mu.x)*rsqrtf(va.x + 1e-5f) + be.x + xv.x;
    o.y = ga.y*((y.y + b.y) - mu.y)*rsqrtf(va.y + 1e-5f) + be.y + xv.y;
    o.z = ga.z*((y.z + b.z) - mu.z)*rsqrtf(va.z + 1e-5f) + be.z + xv.z;
    o.w = ga.w*((y.w + b.w) - mu.w)*rsqrtf(va.w + 1e-5f) + be.w + xv.w;
    ((float4*)out)[i] = o;
}

// ---------------- launch ----------------
extern "C" void kernel_launch(void* const* d_in, const int* in_sizes, int n_in,
                              void* d_out, int out_size)
{
    const float* x    = (const float*)d_in[0];
    const float* Wq   = (const float*)d_in[1];
    const float* bq   = (const float*)d_in[2];
    const float* Wk   = (const float*)d_in[3];
    const float* bk   = (const float*)d_in[4];
    const float* Wv   = (const float*)d_in[5];
    const float* Wp   = (const float*)d_in[6];
    const float* bp   = (const float*)d_in[7];
    const float* bn_q = (const float*)d_in[8];
    const float* bn_k = (const float*)d_in[9];
    const float* bn_v = (const float*)d_in[10];
    const float* bn_p = (const float*)d_in[11];
    float* out  = (float*)d_out;
    float* vout = (out_size >= 2*TBNC) ? (out + TBNC) : nullptr;

    cudaFuncSetAttribute(gemm_mma_kernel, cudaFuncAttributeMaxDynamicSharedMemorySize, GSMEM_BYTES);

    lif_x_kernel<<<(BNC/4 + 255)/256, 256>>>(x);
    wsplit_kernel<<<256, 256>>>(Wq, 0);
    wsplit_kernel<<<256, 256>>>(Wk, 1);
    wsplit_kernel<<<256, 256>>>(Wv, 2);
    wsplit_kernel<<<256, 256>>>(Wp, 3);

    const int GG = 512*4;   // (65536/128) x (512/128)

    // K, then V, then kv, then Q (att fused), then P
    gemm_mma_kernel<<<GG, 256, GSMEM_BYTES>>>(1, 0);
    lif_bn_kernel<<<(BNC/4 + 255)/256, 256>>>(bk, bn_k, 1, nullptr);

    gemm_mma_kernel<<<GG, 256, GSMEM_BYTES>>>(2, 0);
    lif_bn_kernel<<<(BNC/4 + 255)/256, 256>>>(nullptr, bn_v, 2, vout);

    kv_count_kernel<<<TT*BB*8, 256>>>();
    lif_kv_kernel<<<(BB*8*64 + 255)/256, 256>>>();

    gemm_mma_kernel<<<GG, 256, GSMEM_BYTES>>>(0, 0);
    lif_bn_kernel<<<(BNC/4 + 255)/256, 256>>>(bq, bn_q, 0, nullptr);

    gemm_mma_kernel<<<GG, 256, GSMEM_BYTES>>>(3, 1);
    out_kernel<<<(TBNC/4 + 255)/256, 256>>>(x, bp, bn_p, out);
}